// round 17
// baseline (speedup 1.0000x reference)
#include <cuda_runtime.h>
#include <cstdint>

// ParabolicPool2D: out[b,c,i,j] = max_{p,q in 0..2} f[b,c,2i+p,2j+q] + h[c,p,q]
// h[c,p,q] = -t[c]*(zp^2+zq^2)/2 -> separable with s = t[c]/2:
//   colmax[r][j] = max(f[r][2j]-s, f[r][2j+1], f[r][2j+2]-s)
//   out[i][j]    = max(colmax[2i]-s, colmax[2i+1], colmax[2i+2]-s)
//
// Block = one (image, 8-output-row tile), 128 threads, 17.5KB smem ->
// 12 blocks/SM (48 warps, 12 concurrent bulk read streams per SM).
// Reads: FOUR cp.async.bulk chunks (rows 0-4 / 5-8 / 9-12 / 13-16) with
//   per-warp differentiated mbarrier waits: warps 0-1 start computing after
//   only 5KB lands; each phase waits only on the chunks its rows need.
// Writes: direct __stcs scalar stores.

#define Wd 256
#define OWd 127
#define OHd 127

#define NIN_MAX 17

__device__ __forceinline__ uint32_t smem_u32(const void* p) {
    return (uint32_t)__cvta_generic_to_shared(p);
}

__device__ __forceinline__ void mbar_wait(uint32_t mb, uint32_t parity) {
    asm volatile(
        "{\n\t.reg .pred P;\n\t"
        "W_%=:\n\t"
        "mbarrier.try_wait.parity.acquire.cta.shared::cta.b64 P, [%0], %1, 0x989680;\n\t"
        "@P bra.uni D_%=;\n\t"
        "bra.uni W_%=;\n\t"
        "D_%=:\n\t}"
        :: "r"(mb), "r"(parity) : "memory");
}

__device__ __forceinline__ void cm_row(const float* __restrict__ sr, int lane,
                                       float s, float cm[4]) {
    float4 a = *(const float4*)(sr + 4 * lane);
    float4 b = *(const float4*)(sr + 4 * lane + 128);
    float h0 = (lane == 0) ? b.x : a.x;
    int src = (lane + 1) & 31;
    float n0 = __shfl_sync(0xffffffffu, h0, src);   // col 4L+4
    float n1 = __shfl_sync(0xffffffffu, b.x, src);  // col 4L+132 (lane31 unused)
    cm[0] = fmaxf(fmaxf(a.x - s, a.y), a.z - s);    // out col 2L
    cm[1] = fmaxf(fmaxf(a.z - s, a.w), n0 - s);     // out col 2L+1
    cm[2] = fmaxf(fmaxf(b.x - s, b.y), b.z - s);    // out col 2L+64
    cm[3] = fmaxf(fmaxf(b.z - s, b.w), n1 - s);     // out col 2L+65
}

__device__ __forceinline__ void do_row(const float* __restrict__ buf, int i,
                                       float* __restrict__ op, int i0,
                                       int lane, int j0, bool lastlane, float s) {
    const float* r0p = buf + (size_t)(2 * i) * Wd;
    float cmA[4], cmB[4], cmC[4];
    cm_row(r0p,          lane, s, cmA);
    cm_row(r0p + Wd,     lane, s, cmB);
    cm_row(r0p + 2 * Wd, lane, s, cmC);

    float o0 = fmaxf(fmaxf(cmA[0] - s, cmB[0]), cmC[0] - s);
    float o1 = fmaxf(fmaxf(cmA[1] - s, cmB[1]), cmC[1] - s);
    float o2 = fmaxf(fmaxf(cmA[2] - s, cmB[2]), cmC[2] - s);
    float o3 = fmaxf(fmaxf(cmA[3] - s, cmB[3]), cmC[3] - s);

    float* orow = op + (size_t)(i0 + i) * OWd;
    __stcs(orow + j0, o0);
    __stcs(orow + j0 + 1, o1);
    __stcs(orow + j0 + 64, o2);
    if (!lastlane) __stcs(orow + j0 + 65, o3);
}

__global__ void __launch_bounds__(128, 12)
parabolic_pool2d_kernel(const float* __restrict__ f,
                        const float* __restrict__ t,
                        float* __restrict__ out) {
    __shared__ __align__(128) float smi[NIN_MAX * Wd];  // 17 input rows (17408 B)
    __shared__ __align__(8) unsigned long long mbar[4];

    int bid  = blockIdx.x;
    int img  = bid >> 4;                 // image = b*128 + c
    int tile = bid & 15;                 // 8-output-row tile within image
    int i0 = tile << 3;
    int nout = min(8, OHd - i0);         // 8, or 7 for tile 15
    int nin  = 2 * nout + 1;             // 17 or 15 input rows

    const float* src = f + (size_t)img * (256 * Wd) + (size_t)(i0 << 1) * Wd;

    // chunks: rows [0,5) [5,9) [9,13) [13,nin)
    const int coff[4] = {0, 5, 9, 13};
    int csz[4];
    csz[0] = 5; csz[1] = 4; csz[2] = 4; csz[3] = nin - 13;   // 4 or 2

    uint32_t smi_a = smem_u32(smi);
    uint32_t mb[4];
#pragma unroll
    for (int q = 0; q < 4; q++) mb[q] = smem_u32(&mbar[q]);

    if (threadIdx.x == 0) {
#pragma unroll
        for (int q = 0; q < 4; q++)
            asm volatile("mbarrier.init.shared.b64 [%0], 1;" :: "r"(mb[q]) : "memory");
    }
    __syncthreads();
    if (threadIdx.x == 0) {
#pragma unroll
        for (int q = 0; q < 4; q++) {
            int bytes = csz[q] * (Wd * 4);
            asm volatile("mbarrier.arrive.expect_tx.shared.b64 _, [%0], %1;"
                         :: "r"(mb[q]), "r"(bytes) : "memory");
            asm volatile("cp.async.bulk.shared::cta.global.mbarrier::complete_tx::bytes"
                         " [%0], [%1], %2, [%3];"
                         :: "r"(smi_a + coff[q] * Wd * 4), "l"(src + coff[q] * Wd),
                            "r"(bytes), "r"(mb[q]) : "memory");
        }
    }

    float s = 0.5f * __ldg(t + (img & 127));
    float* op = out + (size_t)img * (OHd * OWd);
    int tid  = threadIdx.x;
    int w    = tid >> 5;                 // 0..3
    int lane = tid & 31;
    int j0   = 2 * lane;
    bool lastlane = (lane == 31);

    // phase 1: output row w needs input rows 2w..2w+2
    //   w=0,1 -> chunk0 (rows 0-4); w=2,3 -> chunk0+chunk1 (rows 0-8)
    mbar_wait(mb[0], 0);
    if (w >= 2) mbar_wait(mb[1], 0);
    do_row(smi, w, op, i0, lane, j0, lastlane, s);

    // phase 2: output row w+4 needs input rows 2w+8..2w+10
    //   w=0 -> rows 8-10:  chunk1+chunk2
    //   w=1 -> rows 10-12: chunk2
    //   w=2 -> rows 12-14: chunk2+chunk3
    //   w=3 -> rows 14-16: chunk3
    if (w == 0) mbar_wait(mb[1], 0);
    if (w <= 2) mbar_wait(mb[2], 0);
    if (w >= 2) mbar_wait(mb[3], 0);
    int i = w + 4;
    if (i < nout)
        do_row(smi, i, op, i0, lane, j0, lastlane, s);
}

extern "C" void kernel_launch(void* const* d_in, const int* in_sizes, int n_in,
                              void* d_out, int out_size) {
    const float* f = (const float*)d_in[0];   // [16,128,256,256] fp32
    const float* t = (const float*)d_in[1];   // [128] fp32
    float* out = (float*)d_out;               // [16,128,127,127] fp32
    // 2048 images * 16 tiles = 32768 blocks, 128 threads each
    parabolic_pool2d_kernel<<<32768, 128>>>(f, t, out);
}